// round 7
// baseline (speedup 1.0000x reference)
#include <cuda_runtime.h>
#include <cuda_bf16.h>

// Cutout: out = x with a 16x16 box (centered at (cy[b], cx[b])) zeroed per image.
// x: [B=256, C=3, H=224, W=224] fp32 contiguous. cy, cx: [1,256] int32.
//
// Streaming masked copy. Each thread owns 8 CONSECUTIVE float4 (128 bytes),
// front-batched loads (MLP=8) via one base pointer + immediate offsets.
// W4 = 56 = 7 x 8, so each image row = exactly 7 threads; a thread never
// crosses a row boundary -> one (b,h,w) decomposition per thread.
// Streaming cache hints (__ldcs/__stcs): zero reuse, evict-first.

#define B 256
#define C 3
#define H 224
#define W 224
#define HALF 8

#define W4      (W / 4)            // 56
#define TPR     (W4 / 8)           // 7 threads per row
#define TOTAL_T (B * C * H * TPR)  // 1,204,224 threads
#define NBLK    (TOTAL_T / 256)    // 4704 (exact)

__global__ void __launch_bounds__(256) cutout_kernel(
    const float4* __restrict__ x,
    const int*    __restrict__ cy,
    const int*    __restrict__ cx,
    float4*       __restrict__ out)
{
    int t = blockIdx.x * blockDim.x + threadIdx.x;   // exact grid, no bounds check

    // t = ((b*C + c)*H + h)*7 + w8
    int w8 = t % TPR;
    int p  = t / TPR;          // (b*C + c)*H + h
    int h  = p % H;
    int b  = p / (C * H);

    const float4* src = x + (size_t)t * 8;

    // Front-batch 8 independent 128-bit streaming loads (MLP=8).
    float4 v0 = __ldcs(src + 0);
    float4 v1 = __ldcs(src + 1);
    float4 v2 = __ldcs(src + 2);
    float4 v3 = __ldcs(src + 3);
    float4 v4 = __ldcs(src + 4);
    float4 v5 = __ldcs(src + 5);
    float4 v6 = __ldcs(src + 6);
    float4 v7 = __ldcs(src + 7);

    int yc = __ldg(&cy[b]);
    if (h >= yc - HALF && h < yc + HALF) {
        int xc = __ldg(&cx[b]);
        int x0 = xc - HALF, x1 = xc + HALF;
        int wb = w8 * 32;      // first pixel column covered by this thread

        #define APPLY(v, base)                                              \
            {                                                               \
                int W0 = (base);                                            \
                if (W0 + 0 >= x0 && W0 + 0 < x1) (v).x = 0.0f;              \
                if (W0 + 1 >= x0 && W0 + 1 < x1) (v).y = 0.0f;              \
                if (W0 + 2 >= x0 && W0 + 2 < x1) (v).z = 0.0f;              \
                if (W0 + 3 >= x0 && W0 + 3 < x1) (v).w = 0.0f;              \
            }

        APPLY(v0, wb + 0);
        APPLY(v1, wb + 4);
        APPLY(v2, wb + 8);
        APPLY(v3, wb + 12);
        APPLY(v4, wb + 16);
        APPLY(v5, wb + 20);
        APPLY(v6, wb + 24);
        APPLY(v7, wb + 28);
        #undef APPLY
    }

    float4* dst = out + (size_t)t * 8;
    __stcs(dst + 0, v0);
    __stcs(dst + 1, v1);
    __stcs(dst + 2, v2);
    __stcs(dst + 3, v3);
    __stcs(dst + 4, v4);
    __stcs(dst + 5, v5);
    __stcs(dst + 6, v6);
    __stcs(dst + 7, v7);
}

extern "C" void kernel_launch(void* const* d_in, const int* in_sizes, int n_in,
                              void* d_out, int out_size)
{
    const float4* x   = (const float4*)d_in[0];
    const int*    cy  = (const int*)   d_in[1];
    const int*    cx  = (const int*)   d_in[2];
    float4*       out = (float4*)d_out;

    cutout_kernel<<<NBLK, 256>>>(x, cy, cx, out);
}

// round 8
// speedup vs baseline: 1.6305x; 1.6305x over previous
#include <cuda_runtime.h>
#include <cuda_bf16.h>

// Cutout: out = x with a 16x16 box (centered at (cy[b], cx[b])) zeroed per image.
// x: [B=256, C=3, H=224, W=224] fp32 contiguous. cy, cx: [1,256] int32.
//
// Warp-COALESCED streaming masked copy: consecutive threads -> consecutive
// float4s (R7 post-mortem: per-lane-contiguous layout shatters coalescing and
// binds on L1 wavefronts). Unroll x8 with stride CHUNK = TOTAL4/8 = 32 images,
// so all 8 sub-elements share (c,h,w); only b advances by 32. Front-batched
// independent loads give MLP=8.

#define B 256
#define C 3
#define H 224
#define W 224
#define HALF 8

#define W4     (W / 4)            // 56
#define HW4    (H * W4)           // 12544
#define CHW4   (C * HW4)          // 37632
#define TOTAL4 (B * CHW4)         // 9,633,792
#define UNROLL 8
#define CHUNK  (TOTAL4 / UNROLL)  // 1,204,224 == 32 * CHW4 (b advances by 32)
#define NBLK   (CHUNK / 256)      // 4704 (exact)

__global__ void __launch_bounds__(256) cutout_kernel(
    const float4* __restrict__ x,
    const int*    __restrict__ cy,
    const int*    __restrict__ cx,
    float4*       __restrict__ out)
{
    int i = blockIdx.x * blockDim.x + threadIdx.x;   // exact grid, no bounds check

    // Decompose once: i -> (b0, h, w). Sub-element j: b_j = b0 + 32*j, same (c,h,w).
    int b0   = i / CHW4;              // 0..31
    int rem  = i - b0 * CHW4;
    int hw4  = rem % HW4;
    int h    = hw4 / W4;
    int w    = (hw4 - h * W4) * 4;    // first of 4 consecutive W-coords

    // Front-batch 8 independent warp-coalesced 128-bit streaming loads (MLP=8).
    float4 v0 = __ldcs(x + i + 0 * CHUNK);
    float4 v1 = __ldcs(x + i + 1 * CHUNK);
    float4 v2 = __ldcs(x + i + 2 * CHUNK);
    float4 v3 = __ldcs(x + i + 3 * CHUNK);
    float4 v4 = __ldcs(x + i + 4 * CHUNK);
    float4 v5 = __ldcs(x + i + 5 * CHUNK);
    float4 v6 = __ldcs(x + i + 6 * CHUNK);
    float4 v7 = __ldcs(x + i + 7 * CHUNK);

    #define APPLY(v, j)                                                     \
        {                                                                   \
            int yc = __ldg(&cy[b0 + 32 * (j)]);                             \
            if (h >= yc - HALF && h < yc + HALF) {                          \
                int xc = __ldg(&cx[b0 + 32 * (j)]);                         \
                int x0 = xc - HALF, x1 = xc + HALF;                         \
                if (w + 0 >= x0 && w + 0 < x1) (v).x = 0.0f;                \
                if (w + 1 >= x0 && w + 1 < x1) (v).y = 0.0f;                \
                if (w + 2 >= x0 && w + 2 < x1) (v).z = 0.0f;                \
                if (w + 3 >= x0 && w + 3 < x1) (v).w = 0.0f;                \
            }                                                               \
        }

    APPLY(v0, 0);
    APPLY(v1, 1);
    APPLY(v2, 2);
    APPLY(v3, 3);
    APPLY(v4, 4);
    APPLY(v5, 5);
    APPLY(v6, 6);
    APPLY(v7, 7);
    #undef APPLY

    __stcs(out + i + 0 * CHUNK, v0);
    __stcs(out + i + 1 * CHUNK, v1);
    __stcs(out + i + 2 * CHUNK, v2);
    __stcs(out + i + 3 * CHUNK, v3);
    __stcs(out + i + 4 * CHUNK, v4);
    __stcs(out + i + 5 * CHUNK, v5);
    __stcs(out + i + 6 * CHUNK, v6);
    __stcs(out + i + 7 * CHUNK, v7);
}

extern "C" void kernel_launch(void* const* d_in, const int* in_sizes, int n_in,
                              void* d_out, int out_size)
{
    const float4* x   = (const float4*)d_in[0];
    const int*    cy  = (const int*)   d_in[1];
    const int*    cx  = (const int*)   d_in[2];
    float4*       out = (float4*)d_out;

    cutout_kernel<<<NBLK, 256>>>(x, cy, cx, out);
}